// round 6
// baseline (speedup 1.0000x reference)
#include <cuda_runtime.h>
#include <limits.h>

#define N_NODES 100000
#define E_EDGES 1600000
#define E_TOT   1700000   /* E + N self loops */
#define F_IN    128
#define HID     32
#define HEADS   4
#define F1      128       /* HEADS*HID */
#define CLASSES 10
#define NEG     0.2f

// ---------------- scratch (static device globals; no allocation) ----------------
__device__ float g_xl1[(size_t)N_NODES * F1];
__device__ float g_xr1[(size_t)N_NODES * F1];
__device__ float g_h  [(size_t)N_NODES * F1];      // layer1 aggregate (+b1)
__device__ float g_sc1[(size_t)E_TOT * HEADS];     // scores, then weights w
__device__ int   g_m1 [N_NODES * HEADS];           // ordered-int max
__device__ float g_d1 [N_NODES * HEADS];           // softmax denominators
__device__ float g_xl2[N_NODES * CLASSES];
__device__ float g_xr2[N_NODES * CLASSES];
__device__ float g_sc2[E_TOT];
__device__ int   g_m2 [N_NODES];
__device__ float g_d2 [N_NODES];

// order-preserving float<->int for atomicMax
__device__ __forceinline__ int f2ord(float f) {
    int i = __float_as_int(f);
    return i >= 0 ? i : i ^ 0x7FFFFFFF;
}
__device__ __forceinline__ float ord2f(int i) {
    return __int_as_float(i >= 0 ? i : i ^ 0x7FFFFFFF);
}
__device__ __forceinline__ float lrelu(float v) {
    return v > 0.f ? v : NEG * v;
}

// ---------------- GEMM1: xl1 = x@W1l, xr1 = x@W1r  (64x64 tile, K chunked) ----------------
__global__ void gemm1_kernel(const float* __restrict__ x,
                             const float* __restrict__ W1l,
                             const float* __restrict__ W1r) {
    __shared__ float As[64][68];   // 64 rows x 64 k (padded)
    __shared__ float Bs[64][64];   // 64 k x 64 cols
    const int by = blockIdx.y;                 // 0..3
    const float* __restrict__ W = (by < 2) ? W1l : W1r;
    float* __restrict__ out = (by < 2) ? g_xl1 : g_xr1;
    const int colbase = (by & 1) * 64;
    const int row0 = blockIdx.x * 64;
    const int tid = threadIdx.x;

    const int r = (tid >> 4) * 4;   // 0..60
    const int c = (tid & 15) * 4;   // 0..60
    float acc[4][4] = {};

    for (int kk = 0; kk < F_IN; kk += 64) {
        // load A chunk: 64 rows x 64 k
        for (int i = tid; i < 64 * 16; i += 256) {
            int rr = i >> 4, c4 = (i & 15) << 2;
            float4 v = make_float4(0.f, 0.f, 0.f, 0.f);
            if (row0 + rr < N_NODES)
                v = *reinterpret_cast<const float4*>(&x[(size_t)(row0 + rr) * F_IN + kk + c4]);
            As[rr][c4 + 0] = v.x; As[rr][c4 + 1] = v.y;
            As[rr][c4 + 2] = v.z; As[rr][c4 + 3] = v.w;
        }
        // load B chunk: 64 k x 64 cols
        for (int i = tid; i < 64 * 16; i += 256) {
            int k = i >> 4, c4 = (i & 15) << 2;
            *reinterpret_cast<float4*>(&Bs[k][c4]) =
                *reinterpret_cast<const float4*>(&W[(size_t)(kk + k) * F1 + colbase + c4]);
        }
        __syncthreads();
        #pragma unroll 8
        for (int k = 0; k < 64; k++) {
            float a0 = As[r + 0][k], a1 = As[r + 1][k],
                  a2 = As[r + 2][k], a3 = As[r + 3][k];
            float4 b = *reinterpret_cast<float4*>(&Bs[k][c]);
            acc[0][0] += a0 * b.x; acc[0][1] += a0 * b.y; acc[0][2] += a0 * b.z; acc[0][3] += a0 * b.w;
            acc[1][0] += a1 * b.x; acc[1][1] += a1 * b.y; acc[1][2] += a1 * b.z; acc[1][3] += a1 * b.w;
            acc[2][0] += a2 * b.x; acc[2][1] += a2 * b.y; acc[2][2] += a2 * b.z; acc[2][3] += a2 * b.w;
            acc[3][0] += a3 * b.x; acc[3][1] += a3 * b.y; acc[3][2] += a3 * b.z; acc[3][3] += a3 * b.w;
        }
        __syncthreads();
    }
    #pragma unroll
    for (int i = 0; i < 4; i++) {
        int row = row0 + r + i;
        if (row < N_NODES) {
            float4 v = make_float4(acc[i][0], acc[i][1], acc[i][2], acc[i][3]);
            *reinterpret_cast<float4*>(&out[(size_t)row * F1 + colbase + c]) = v;
        }
    }
}

// ---------------- init layer 1 ----------------
__global__ void init1_kernel(const float* __restrict__ b1) {
    int i = blockIdx.x * blockDim.x + threadIdx.x;
    if (i < N_NODES * F1) g_h[i] = b1[i & (F1 - 1)];
    if (i < N_NODES * HEADS) { g_m1[i] = INT_MIN; g_d1[i] = 0.f; }
}

// ---------------- edge pass A1: scores + segment max (warp per edge) ----------------
__global__ void edge_score1_kernel(const int* __restrict__ ei,
                                   const float* __restrict__ att1) {
    int gw = (blockIdx.x * blockDim.x + threadIdx.x) >> 5;
    int lane = threadIdx.x & 31;
    if (gw >= E_TOT) return;
    int src, dst;
    if (gw < E_EDGES) { src = ei[gw]; dst = ei[E_EDGES + gw]; }
    else              { src = dst = gw - E_EDGES; }

    float4 a = reinterpret_cast<const float4*>(g_xl1 + (size_t)src * F1)[lane];
    float4 b = reinterpret_cast<const float4*>(g_xr1 + (size_t)dst * F1)[lane];
    float4 w = reinterpret_cast<const float4*>(att1)[lane];
    float t = lrelu(a.x + b.x) * w.x + lrelu(a.y + b.y) * w.y
            + lrelu(a.z + b.z) * w.z + lrelu(a.w + b.w) * w.w;
    // reduce within groups of 8 lanes (one head = 8 lanes x 4 channels)
    t += __shfl_xor_sync(0xFFFFFFFFu, t, 1);
    t += __shfl_xor_sync(0xFFFFFFFFu, t, 2);
    t += __shfl_xor_sync(0xFFFFFFFFu, t, 4);
    if ((lane & 7) == 0) {
        int h = lane >> 3;
        g_sc1[(size_t)gw * HEADS + h] = t;
        atomicMax(&g_m1[dst * HEADS + h], f2ord(t));
    }
}

// ---------------- edge pass B1: w = exp(s - m), denom ----------------
__global__ void edge_soft1_kernel(const int* __restrict__ ei) {
    int idx = blockIdx.x * blockDim.x + threadIdx.x;
    if (idx >= E_TOT * HEADS) return;
    int e = idx >> 2, h = idx & 3;
    int dst = (e < E_EDGES) ? ei[E_EDGES + e] : e - E_EDGES;
    float m = ord2f(g_m1[dst * HEADS + h]);
    float w = __expf(g_sc1[idx] - m);
    g_sc1[idx] = w;
    atomicAdd(&g_d1[dst * HEADS + h], w);
}

// ---------------- edge pass C1: out[dst] += xl1[src]*alpha (warp per edge) ----------------
__global__ void edge_agg1_kernel(const int* __restrict__ ei) {
    int gw = (blockIdx.x * blockDim.x + threadIdx.x) >> 5;
    int lane = threadIdx.x & 31;
    if (gw >= E_TOT) return;
    int src, dst;
    if (gw < E_EDGES) { src = ei[gw]; dst = ei[E_EDGES + gw]; }
    else              { src = dst = gw - E_EDGES; }
    int h = lane >> 3;
    float alpha = g_sc1[(size_t)gw * HEADS + h] / g_d1[dst * HEADS + h];
    float4 a = reinterpret_cast<const float4*>(g_xl1 + (size_t)src * F1)[lane];
    float* o = g_h + (size_t)dst * F1 + lane * 4;
    atomicAdd(o + 0, a.x * alpha);
    atomicAdd(o + 1, a.y * alpha);
    atomicAdd(o + 2, a.z * alpha);
    atomicAdd(o + 3, a.w * alpha);
}

// ---------------- GEMM2: xl2/xr2 = relu(h) @ {W2l,W2r}  (warp per node) ----------------
__global__ void gemm2_kernel(const float* __restrict__ W2l,
                             const float* __restrict__ W2r) {
    __shared__ float Ws[128][21];   // 20 cols used, padded to 21 (odd stride)
    int tid = threadIdx.x;
    for (int i = tid; i < 128 * CLASSES; i += blockDim.x) {
        int k = i / CLASSES, j = i - k * CLASSES;
        Ws[k][j]           = W2l[i];
        Ws[k][j + CLASSES] = W2r[i];
    }
    __syncthreads();
    int warps = blockDim.x >> 5;
    int node = blockIdx.x * warps + (tid >> 5);
    int lane = tid & 31;
    if (node >= N_NODES) return;
    const float* hrow = g_h + (size_t)node * F1;
    float r0 = fmaxf(hrow[lane +  0], 0.f);
    float r1 = fmaxf(hrow[lane + 32], 0.f);
    float r2 = fmaxf(hrow[lane + 64], 0.f);
    float r3 = fmaxf(hrow[lane + 96], 0.f);
    #pragma unroll
    for (int j = 0; j < 2 * CLASSES; j++) {
        float s = r0 * Ws[lane][j] + r1 * Ws[lane + 32][j]
                + r2 * Ws[lane + 64][j] + r3 * Ws[lane + 96][j];
        #pragma unroll
        for (int off = 16; off; off >>= 1) s += __shfl_xor_sync(0xFFFFFFFFu, s, off);
        if (lane == 0) {
            if (j < CLASSES) g_xl2[node * CLASSES + j] = s;
            else             g_xr2[node * CLASSES + j - CLASSES] = s;
        }
    }
}

// ---------------- init layer 2 + output ----------------
__global__ void init2_kernel(float* __restrict__ out, const float* __restrict__ b2) {
    int i = blockIdx.x * blockDim.x + threadIdx.x;
    if (i < N_NODES * CLASSES) {
        int c = i % CLASSES;
        out[i] = b2[c];
    }
    if (i < N_NODES) { g_m2[i] = INT_MIN; g_d2[i] = 0.f; }
}

// ---------------- edge pass A2 ----------------
__global__ void edge_score2_kernel(const int* __restrict__ ei,
                                   const float* __restrict__ att2) {
    int e = blockIdx.x * blockDim.x + threadIdx.x;
    if (e >= E_TOT) return;
    int src, dst;
    if (e < E_EDGES) { src = ei[e]; dst = ei[E_EDGES + e]; }
    else             { src = dst = e - E_EDGES; }
    const float* xl = g_xl2 + src * CLASSES;
    const float* xr = g_xr2 + dst * CLASSES;
    float s = 0.f;
    #pragma unroll
    for (int c = 0; c < CLASSES; c++)
        s += lrelu(xl[c] + xr[c]) * att2[c];
    g_sc2[e] = s;
    atomicMax(&g_m2[dst], f2ord(s));
}

// ---------------- edge pass B2 ----------------
__global__ void edge_soft2_kernel(const int* __restrict__ ei) {
    int e = blockIdx.x * blockDim.x + threadIdx.x;
    if (e >= E_TOT) return;
    int dst = (e < E_EDGES) ? ei[E_EDGES + e] : e - E_EDGES;
    float m = ord2f(g_m2[dst]);
    float w = __expf(g_sc2[e] - m);
    g_sc2[e] = w;
    atomicAdd(&g_d2[dst], w);
}

// ---------------- edge pass C2 ----------------
__global__ void edge_agg2_kernel(const int* __restrict__ ei,
                                 float* __restrict__ out) {
    int e = blockIdx.x * blockDim.x + threadIdx.x;
    if (e >= E_TOT) return;
    int src, dst;
    if (e < E_EDGES) { src = ei[e]; dst = ei[E_EDGES + e]; }
    else             { src = dst = e - E_EDGES; }
    float alpha = g_sc2[e] / g_d2[dst];
    const float* xl = g_xl2 + src * CLASSES;
    float* o = out + dst * CLASSES;
    #pragma unroll
    for (int c = 0; c < CLASSES; c++)
        atomicAdd(o + c, xl[c] * alpha);
}

// ---------------- launch ----------------
extern "C" void kernel_launch(void* const* d_in, const int* in_sizes, int n_in,
                              void* d_out, int out_size) {
    const float* x    = (const float*)d_in[0];
    const int*   ei   = (const int*)d_in[1];     // int32! (JAX x64 disabled demotes int64)
    const float* W1l  = (const float*)d_in[2];
    const float* W1r  = (const float*)d_in[3];
    const float* att1 = (const float*)d_in[4];
    const float* b1   = (const float*)d_in[5];
    const float* W2l  = (const float*)d_in[6];
    const float* W2r  = (const float*)d_in[7];
    const float* att2 = (const float*)d_in[8];
    const float* b2   = (const float*)d_in[9];
    float* out = (float*)d_out;

    // layer 1
    {
        dim3 grid((N_NODES + 63) / 64, 4);
        gemm1_kernel<<<grid, 256>>>(x, W1l, W1r);
    }
    init1_kernel<<<(N_NODES * F1 + 255) / 256, 256>>>(b1);
    edge_score1_kernel<<<(E_TOT * 32 + 255) / 256, 256>>>(ei, att1);
    edge_soft1_kernel<<<(E_TOT * HEADS + 255) / 256, 256>>>(ei);
    edge_agg1_kernel<<<(E_TOT * 32 + 255) / 256, 256>>>(ei);

    // layer 2
    gemm2_kernel<<<(N_NODES + 7) / 8, 256>>>(W2l, W2r);
    init2_kernel<<<(N_NODES * CLASSES + 255) / 256, 256>>>(out, b2);
    edge_score2_kernel<<<(E_TOT + 255) / 256, 256>>>(ei, att2);
    edge_soft2_kernel<<<(E_TOT + 255) / 256, 256>>>(ei);
    edge_agg2_kernel<<<(E_TOT + 255) / 256, 256>>>(ei, out);
}

// round 7
// speedup vs baseline: 1.3456x; 1.3456x over previous
#include <cuda_runtime.h>
#include <limits.h>

#define N_NODES 100000
#define E_EDGES 1600000
#define E_TOT   1700000   /* E + N self loops */
#define F_IN    128
#define HID     32
#define HEADS   4
#define F1      128       /* HEADS*HID */
#define CLASSES 10
#define NEG     0.2f

// ---------------- scratch (static device globals; no allocation) ----------------
__device__ float g_xl1[(size_t)N_NODES * F1];
__device__ float g_xr1[(size_t)N_NODES * F1];
__device__ float g_h  [(size_t)N_NODES * F1];      // layer1 output (post-softmax agg + b1)
__device__ float g_xl2[N_NODES * CLASSES];
__device__ float g_xr2[N_NODES * CLASSES];
// CSR by destination
__device__ int g_deg   [N_NODES];
__device__ int g_rowptr[N_NODES + 1];
__device__ int g_cursor[N_NODES];
__device__ int g_esrc  [E_TOT];

__device__ __forceinline__ float lrelu(float v) {
    return v > 0.f ? v : NEG * v;
}

// ================= CSR build =================
__global__ void deg_init_kernel() {
    int i = blockIdx.x * blockDim.x + threadIdx.x;
    if (i < N_NODES) g_deg[i] = 1;   // self loop
}

__global__ void deg_count_kernel(const int* __restrict__ ei) {
    int e = blockIdx.x * blockDim.x + threadIdx.x;
    if (e < E_EDGES) atomicAdd(&g_deg[ei[E_EDGES + e]], 1);
}

__global__ void csr_scan_kernel() {
    __shared__ int wsums[32];
    const int T = 1024;
    const int per = (N_NODES + T - 1) / T;   // 98
    int t = threadIdx.x;
    int base = t * per;
    int sum = 0;
    for (int i = 0; i < per; i++) {
        int idx = base + i;
        if (idx < N_NODES) sum += g_deg[idx];
    }
    int lane = t & 31, wid = t >> 5;
    int v = sum;
    #pragma unroll
    for (int off = 1; off < 32; off <<= 1) {
        int nv = __shfl_up_sync(0xFFFFFFFFu, v, off);
        if (lane >= off) v += nv;
    }
    if (lane == 31) wsums[wid] = v;
    __syncthreads();
    if (wid == 0) {
        int w = wsums[lane];
        #pragma unroll
        for (int off = 1; off < 32; off <<= 1) {
            int nv = __shfl_up_sync(0xFFFFFFFFu, w, off);
            if (lane >= off) w += nv;
        }
        wsums[lane] = w;
    }
    __syncthreads();
    int excl = v - sum + (wid > 0 ? wsums[wid - 1] : 0);
    int run = excl;
    for (int i = 0; i < per; i++) {
        int idx = base + i;
        if (idx < N_NODES) {
            g_rowptr[idx] = run;
            g_cursor[idx] = run;
            run += g_deg[idx];
        }
    }
    if (t == 0) g_rowptr[N_NODES] = E_TOT;
}

__global__ void csr_scatter_kernel(const int* __restrict__ ei) {
    int e = blockIdx.x * blockDim.x + threadIdx.x;
    if (e >= E_TOT) return;
    int src, dst;
    if (e < E_EDGES) { src = ei[e]; dst = ei[E_EDGES + e]; }
    else             { src = dst = e - E_EDGES; }
    int pos = atomicAdd(&g_cursor[dst], 1);
    g_esrc[pos] = src;
}

// ================= GEMM1: xl1 = x@W1l, xr1 = x@W1r  (64x64 tile) =================
__global__ void gemm1_kernel(const float* __restrict__ x,
                             const float* __restrict__ W1l,
                             const float* __restrict__ W1r) {
    __shared__ float As[64][68];
    __shared__ float Bs[64][64];
    const int by = blockIdx.y;                 // 0..3
    const float* __restrict__ W = (by < 2) ? W1l : W1r;
    float* __restrict__ out = (by < 2) ? g_xl1 : g_xr1;
    const int colbase = (by & 1) * 64;
    const int row0 = blockIdx.x * 64;
    const int tid = threadIdx.x;

    const int r = (tid >> 4) * 4;
    const int c = (tid & 15) * 4;
    float acc[4][4] = {};

    for (int kk = 0; kk < F_IN; kk += 64) {
        for (int i = tid; i < 64 * 16; i += 256) {
            int rr = i >> 4, c4 = (i & 15) << 2;
            float4 v = make_float4(0.f, 0.f, 0.f, 0.f);
            if (row0 + rr < N_NODES)
                v = *reinterpret_cast<const float4*>(&x[(size_t)(row0 + rr) * F_IN + kk + c4]);
            As[rr][c4 + 0] = v.x; As[rr][c4 + 1] = v.y;
            As[rr][c4 + 2] = v.z; As[rr][c4 + 3] = v.w;
        }
        for (int i = tid; i < 64 * 16; i += 256) {
            int k = i >> 4, c4 = (i & 15) << 2;
            *reinterpret_cast<float4*>(&Bs[k][c4]) =
                *reinterpret_cast<const float4*>(&W[(size_t)(kk + k) * F1 + colbase + c4]);
        }
        __syncthreads();
        #pragma unroll 8
        for (int k = 0; k < 64; k++) {
            float a0 = As[r + 0][k], a1 = As[r + 1][k],
                  a2 = As[r + 2][k], a3 = As[r + 3][k];
            float4 b = *reinterpret_cast<float4*>(&Bs[k][c]);
            acc[0][0] += a0 * b.x; acc[0][1] += a0 * b.y; acc[0][2] += a0 * b.z; acc[0][3] += a0 * b.w;
            acc[1][0] += a1 * b.x; acc[1][1] += a1 * b.y; acc[1][2] += a1 * b.z; acc[1][3] += a1 * b.w;
            acc[2][0] += a2 * b.x; acc[2][1] += a2 * b.y; acc[2][2] += a2 * b.z; acc[2][3] += a2 * b.w;
            acc[3][0] += a3 * b.x; acc[3][1] += a3 * b.y; acc[3][2] += a3 * b.z; acc[3][3] += a3 * b.w;
        }
        __syncthreads();
    }
    #pragma unroll
    for (int i = 0; i < 4; i++) {
        int row = row0 + r + i;
        if (row < N_NODES) {
            float4 v = make_float4(acc[i][0], acc[i][1], acc[i][2], acc[i][3]);
            *reinterpret_cast<float4*>(&out[(size_t)row * F1 + colbase + c]) = v;
        }
    }
}

// ================= Layer-1 fused: score + softmax + aggregate (warp per node) =================
__global__ void l1_fused_kernel(const float* __restrict__ att1,
                                const float* __restrict__ b1) {
    int n = (blockIdx.x * blockDim.x + threadIdx.x) >> 5;
    int lane = threadIdx.x & 31;
    if (n >= N_NODES) return;
    int begin = g_rowptr[n], end = g_rowptr[n + 1];

    float4 xr = reinterpret_cast<const float4*>(g_xr1 + (size_t)n * F1)[lane];
    float4 aw = reinterpret_cast<const float4*>(att1)[lane];

    // pass 1: per-head max of scores
    float m = -3.402823466e38f;
    for (int p = begin; p < end; p++) {
        int src = __ldg(&g_esrc[p]);
        float4 a = reinterpret_cast<const float4*>(g_xl1 + (size_t)src * F1)[lane];
        float t = lrelu(a.x + xr.x) * aw.x + lrelu(a.y + xr.y) * aw.y
                + lrelu(a.z + xr.z) * aw.z + lrelu(a.w + xr.w) * aw.w;
        t += __shfl_xor_sync(0xFFFFFFFFu, t, 1);
        t += __shfl_xor_sync(0xFFFFFFFFu, t, 2);
        t += __shfl_xor_sync(0xFFFFFFFFu, t, 4);
        m = fmaxf(m, t);
    }
    // pass 2: denom + unnormalized aggregate
    float denom = 0.f;
    float4 acc = make_float4(0.f, 0.f, 0.f, 0.f);
    for (int p = begin; p < end; p++) {
        int src = __ldg(&g_esrc[p]);
        float4 a = reinterpret_cast<const float4*>(g_xl1 + (size_t)src * F1)[lane];
        float t = lrelu(a.x + xr.x) * aw.x + lrelu(a.y + xr.y) * aw.y
                + lrelu(a.z + xr.z) * aw.z + lrelu(a.w + xr.w) * aw.w;
        t += __shfl_xor_sync(0xFFFFFFFFu, t, 1);
        t += __shfl_xor_sync(0xFFFFFFFFu, t, 2);
        t += __shfl_xor_sync(0xFFFFFFFFu, t, 4);
        float w = __expf(t - m);
        denom += w;
        acc.x += w * a.x; acc.y += w * a.y;
        acc.z += w * a.z; acc.w += w * a.w;
    }
    float inv = 1.f / denom;
    float4 bb = reinterpret_cast<const float4*>(b1)[lane];
    float4 o = make_float4(acc.x * inv + bb.x, acc.y * inv + bb.y,
                           acc.z * inv + bb.z, acc.w * inv + bb.w);
    reinterpret_cast<float4*>(g_h + (size_t)n * F1)[lane] = o;
}

// ================= GEMM2: xl2/xr2 = relu(h) @ {W2l,W2r}  (warp per node) =================
__global__ void gemm2_kernel(const float* __restrict__ W2l,
                             const float* __restrict__ W2r) {
    __shared__ float Ws[128][21];
    int tid = threadIdx.x;
    for (int i = tid; i < 128 * CLASSES; i += blockDim.x) {
        int k = i / CLASSES, j = i - k * CLASSES;
        Ws[k][j]           = W2l[i];
        Ws[k][j + CLASSES] = W2r[i];
    }
    __syncthreads();
    int warps = blockDim.x >> 5;
    int node = blockIdx.x * warps + (tid >> 5);
    int lane = tid & 31;
    if (node >= N_NODES) return;
    const float* hrow = g_h + (size_t)node * F1;
    float r0 = fmaxf(hrow[lane +  0], 0.f);
    float r1 = fmaxf(hrow[lane + 32], 0.f);
    float r2 = fmaxf(hrow[lane + 64], 0.f);
    float r3 = fmaxf(hrow[lane + 96], 0.f);
    #pragma unroll
    for (int j = 0; j < 2 * CLASSES; j++) {
        float s = r0 * Ws[lane][j] + r1 * Ws[lane + 32][j]
                + r2 * Ws[lane + 64][j] + r3 * Ws[lane + 96][j];
        #pragma unroll
        for (int off = 16; off; off >>= 1) s += __shfl_xor_sync(0xFFFFFFFFu, s, off);
        if (lane == 0) {
            if (j < CLASSES) g_xl2[node * CLASSES + j] = s;
            else             g_xr2[node * CLASSES + j - CLASSES] = s;
        }
    }
}

// ================= Layer-2 fused (half-warp per node) =================
__global__ void l2_fused_kernel(const float* __restrict__ att2,
                                const float* __restrict__ b2,
                                float* __restrict__ out) {
    int idx = blockIdx.x * blockDim.x + threadIdx.x;
    int n = idx >> 4;
    int l = idx & 15;
    if (n >= N_NODES) return;
    int begin = g_rowptr[n], end = g_rowptr[n + 1];

    float xr = (l < CLASSES) ? g_xr2[n * CLASSES + l] : 0.f;
    float av = (l < CLASSES) ? att2[l] : 0.f;

    float m = -3.402823466e38f;
    for (int p = begin; p < end; p++) {
        int src = __ldg(&g_esrc[p]);
        float xl = (l < CLASSES) ? g_xl2[src * CLASSES + l] : 0.f;
        float t = lrelu(xl + xr) * av;
        t += __shfl_xor_sync(0xFFFFFFFFu, t, 1);
        t += __shfl_xor_sync(0xFFFFFFFFu, t, 2);
        t += __shfl_xor_sync(0xFFFFFFFFu, t, 4);
        t += __shfl_xor_sync(0xFFFFFFFFu, t, 8);
        m = fmaxf(m, t);
    }
    float denom = 0.f, acc = 0.f;
    for (int p = begin; p < end; p++) {
        int src = __ldg(&g_esrc[p]);
        float xl = (l < CLASSES) ? g_xl2[src * CLASSES + l] : 0.f;
        float t = lrelu(xl + xr) * av;
        t += __shfl_xor_sync(0xFFFFFFFFu, t, 1);
        t += __shfl_xor_sync(0xFFFFFFFFu, t, 2);
        t += __shfl_xor_sync(0xFFFFFFFFu, t, 4);
        t += __shfl_xor_sync(0xFFFFFFFFu, t, 8);
        float w = __expf(t - m);
        denom += w;
        acc += w * xl;
    }
    if (l < CLASSES) out[n * CLASSES + l] = acc / denom + b2[l];
}

// ================= launch =================
extern "C" void kernel_launch(void* const* d_in, const int* in_sizes, int n_in,
                              void* d_out, int out_size) {
    const float* x    = (const float*)d_in[0];
    const int*   ei   = (const int*)d_in[1];     // int32 (JAX x64 disabled)
    const float* W1l  = (const float*)d_in[2];
    const float* W1r  = (const float*)d_in[3];
    const float* att1 = (const float*)d_in[4];
    const float* b1   = (const float*)d_in[5];
    const float* W2l  = (const float*)d_in[6];
    const float* W2r  = (const float*)d_in[7];
    const float* att2 = (const float*)d_in[8];
    const float* b2   = (const float*)d_in[9];
    float* out = (float*)d_out;

    // CSR build (by destination)
    deg_init_kernel<<<(N_NODES + 255) / 256, 256>>>();
    deg_count_kernel<<<(E_EDGES + 255) / 256, 256>>>(ei);
    csr_scan_kernel<<<1, 1024>>>();
    csr_scatter_kernel<<<(E_TOT + 255) / 256, 256>>>(ei);

    // layer 1
    {
        dim3 grid((N_NODES + 63) / 64, 4);
        gemm1_kernel<<<grid, 256>>>(x, W1l, W1r);
    }
    l1_fused_kernel<<<(N_NODES * 32 + 255) / 256, 256>>>(att1, b1);

    // layer 2
    gemm2_kernel<<<(N_NODES + 7) / 8, 256>>>(W2l, W2r);
    l2_fused_kernel<<<(N_NODES * 16 + 255) / 256, 256>>>(att2, b2, out);
}